// round 1
// baseline (speedup 1.0000x reference)
#include <cuda_runtime.h>
#include <cstdint>
#include <cstddef>

#define RANK 64
#define WIN  11
#define PADR 5
#define SEG  66   // rows per warp; multiple of WIN so ring indices are static
#define WPB  4    // warps per block

using u64 = unsigned long long;

__device__ __forceinline__ u64 pack2(float lo, float hi){
    u64 r; asm("mov.b64 %0, {%1, %2};" : "=l"(r) : "f"(lo), "f"(hi)); return r;
}
__device__ __forceinline__ void unpack2(u64 v, float& lo, float& hi){
    asm("mov.b64 {%0, %1}, %2;" : "=f"(lo), "=f"(hi) : "l"(v));
}
__device__ __forceinline__ u64 ffma2(u64 a, u64 b, u64 c){
    u64 d; asm("fma.rn.f32x2 %0, %1, %2, %3;" : "=l"(d) : "l"(a), "l"(b), "l"(c)); return d;
}
__device__ __forceinline__ u64 fadd2(u64 a, u64 b){
    u64 d; asm("add.rn.f32x2 %0, %1, %2;" : "=l"(d) : "l"(a), "l"(b)); return d;
}
__device__ __forceinline__ u64 fmul2(u64 a, u64 b){
    u64 d; asm("mul.rn.f32x2 %0, %1, %2;" : "=l"(d) : "l"(a), "l"(b)); return d;
}
__device__ __forceinline__ float ex2f(float x){
    float y; asm("ex2.approx.ftz.f32 %0, %1;" : "=f"(y) : "f"(x)); return y;
}
// Accurate-enough tanh (abs err ~1e-6), cheaper than libm tanhf.
__device__ __forceinline__ float tanh_fast(float x){
    float e = __expf(2.0f * x);
    return 1.0f - __fdividef(2.0f, e + 1.0f);
}

// Load one padded row's two columns (cA, cB) packed into f32x2. OOB -> 0 (zero padding).
__device__ __forceinline__ u64 load_row2(const float* __restrict__ X, int row, int n, int cA, int cB){
    if ((unsigned)row >= (unsigned)n) return 0ull;
    const float* p = X + (size_t)row * RANK;
    return pack2(__ldg(p + cA), __ldg(p + cB));
}

__global__ void __launch_bounds__(WPB * 32)
attn_smooth_kernel(const float* __restrict__ X,   // (n, 64)
                   const float* __restrict__ Wm,  // (64, 64) row-major (out, in)
                   const float* __restrict__ Bv,  // (64,)
                   float* __restrict__ Out,       // (n, 64)
                   int n, int nseg)
{
    const int warp = blockIdx.x * WPB + (threadIdx.x >> 5);
    if (warp >= nseg) return;
    const int lane = threadIdx.x & 31;
    const int cA = lane, cB = lane + 32;
    const int s0 = warp * SEG;

    // --- W rows cA and cB into registers, k packed in adjacent pairs ---
    u64 wA[32], wB[32];
    {
        const ulonglong2* pa = reinterpret_cast<const ulonglong2*>(Wm + (size_t)cA * RANK);
        const ulonglong2* pb = reinterpret_cast<const ulonglong2*>(Wm + (size_t)cB * RANK);
        #pragma unroll
        for (int q = 0; q < 16; q++){
            ulonglong2 ta = pa[q]; wA[2*q] = ta.x; wA[2*q+1] = ta.y;
            ulonglong2 tb = pb[q]; wB[2*q] = tb.x; wB[2*q+1] = tb.y;
        }
    }
    const float bA = Bv[cA], bB = Bv[cB];

    // --- prime the 11-row register ring: rows s0-5 .. s0+4 -> slots 0..9 ---
    u64 xw[WIN];
    #pragma unroll
    for (int j = 0; j < WIN - 1; j++)
        xw[j] = load_row2(X, s0 - PADR + j, n, cA, cB);

    const float KSC = 0.18033688011112042f;  // log2(e) / sqrt(64)

    for (int i0 = 0; i0 < SEG; i0 += WIN) {
        #pragma unroll
        for (int u = 0; u < WIN; u++) {
            const int r = s0 + i0 + u;   // warp-uniform
            if (r < n) {
                // slide: load row r+5 into static slot (u+10) mod 11
                xw[(u + WIN - 1) % WIN] = load_row2(X, r + PADR, n, cA, cB);

                // --- GEMM: v = tanh(x_r @ W^T + b) for cols cA, cB ---
                u64 a0 = 0, a1 = 0, c0 = 0, c1 = 0;
                const ulonglong2* xr = reinterpret_cast<const ulonglong2*>(X + (size_t)r * RANK);
                #pragma unroll
                for (int q = 0; q < 16; q++){
                    ulonglong2 t = xr[q];           // uniform-address LDG.128 (L1-hot)
                    a0 = ffma2(t.x, wA[2*q],     a0);
                    a1 = ffma2(t.y, wA[2*q + 1], a1);
                    c0 = ffma2(t.x, wB[2*q],     c0);
                    c1 = ffma2(t.y, wB[2*q + 1], c1);
                }
                float ae, ao, be, bo;
                unpack2(fadd2(a0, a1), ae, ao);
                unpack2(fadd2(c0, c1), be, bo);
                const float vA = tanh_fast(ae + ao + bA);
                const float vB = tanh_fast(be + bo + bB);
                const u64 vs2 = pack2(vA * KSC, vB * KSC);  // fold log2e/8 into v

                // --- per-lane partial scores for all 11 window positions ---
                float sp[WIN];
                #pragma unroll
                for (int w = 0; w < WIN; w++){
                    float pa, pb;
                    unpack2(fmul2(xw[(u + w) % WIN], vs2), pa, pb);
                    sp[w] = pa + pb;
                }
                // pack 11 scalars (+ -inf pad) into 6 f32x2, butterfly-reduce over 32 lanes
                u64 P[6];
                #pragma unroll
                for (int j = 0; j < 5; j++) P[j] = pack2(sp[2*j], sp[2*j+1]);
                P[5] = pack2(sp[10], -1e30f);
                #pragma unroll
                for (int d = 1; d < 32; d <<= 1){
                    #pragma unroll
                    for (int j = 0; j < 6; j++)
                        P[j] = fadd2(P[j], __shfl_xor_sync(0xffffffffu, P[j], d));
                }
                float s2[12];
                #pragma unroll
                for (int j = 0; j < 6; j++) unpack2(P[j], s2[2*j], s2[2*j+1]);

                // --- softmax (log2 domain, no max-sub needed: |s| bounded small) ---
                float e[WIN];
                #pragma unroll
                for (int w = 0; w < WIN; w++) e[w] = ex2f(s2[w]);
                const float z0 = (e[0] + e[1]) + (e[2] + e[3]);
                const float z1 = (e[4] + e[5]) + (e[6] + e[7]);
                const float z2 = (e[8] + e[9]) + e[10];
                const float rinv = __fdividef(1.0f, z0 + z1 + z2);

                // --- weighted recombination: out = (sum_w e_w * x_{r-5+w}) / Z ---
                u64 o0 = 0, o1 = 0;
                #pragma unroll
                for (int w = 0; w < WIN; w++){
                    const u64 ew = pack2(e[w], e[w]);
                    if (w & 1) o1 = ffma2(ew, xw[(u + w) % WIN], o1);
                    else       o0 = ffma2(ew, xw[(u + w) % WIN], o0);
                }
                float oA, oB;
                unpack2(fmul2(fadd2(o0, o1), pack2(rinv, rinv)), oA, oB);
                float* orow = Out + (size_t)r * RANK;
                orow[cA] = oA;
                orow[cB] = oB;
            }
        }
    }
}

extern "C" void kernel_launch(void* const* d_in, const int* in_sizes, int n_in,
                              void* d_out, int out_size)
{
    const float* X  = (const float*)d_in[0];  // time_factor (n, 64)
    const float* Wm = (const float*)d_in[1];  // W (64, 64)
    const float* Bv = (const float*)d_in[2];  // b (64,)
    float* Out = (float*)d_out;

    const int n = in_sizes[0] / RANK;
    const int nseg = (n + SEG - 1) / SEG;
    const int blocks = (nseg + WPB - 1) / WPB;
    attn_smooth_kernel<<<blocks, WPB * 32>>>(X, Wm, Bv, Out, n, nseg);
}